// round 1
// baseline (speedup 1.0000x reference)
#include <cuda_runtime.h>
#include <cstdint>

// ---------------------------------------------------------------------------
// Problem constants
//   x:   [1, 128, 36, 72, 72]  fp32   (Cin=128, D=36, HW=5184, NVOX=186624)
//   att: [1, 128, 2304, 81]    fp32   (L = 4*576 = 2304, P*P = 81)
//   W:   [128, 128]            fp32
//   b:   [128]                 fp32
//   out: [1, 128, 36, 72, 72]  fp32
//
//   y   = W @ x + b                      (per-voxel channel GEMM)
//   out = leaky_0.2( y * (y + att[c,l,pp]/nz[c,l] + 1) )
//   with l = (d/9)*576 + hw/9, pp = (d%9)*9 + hw%9,
//        nz = count_nonzero(att[c,l,:]) + 1e-5
// ---------------------------------------------------------------------------

#define CIN    128
#define COUT   128
#define DDIM   36
#define HWDIM  5184
#define NVOX   (DDIM * HWDIM)     // 186624
#define PATCH  9
#define PPSQ   81
#define NW     (HWDIM / PATCH)    // 576
#define LPATCH 2304               // (36/9) * 576

#define SMEM_BYTES (2 * 128 * 129 * 4)   // 132096 bytes

// scratch: 1/(nz + 1e-5) per (c, l)  -> 1.18 MB static device buffer
__device__ float g_invnz[COUT * LPATCH];

// ---------------------------------------------------------------------------
// Kernel 1: per-(c,l) inverse nonzero count. One warp per (c,l) row of 81.
// ---------------------------------------------------------------------------
__global__ __launch_bounds__(256) void nz_kernel(const float* __restrict__ att)
{
    int warp_global = (blockIdx.x * blockDim.x + threadIdx.x) >> 5;
    int lane = threadIdx.x & 31;
    if (warp_global >= COUT * LPATCH) return;

    const float* p = att + (size_t)warp_global * PPSQ;
    int cnt = 0;
#pragma unroll
    for (int i = 0; i < 3; i++) {
        int idx = lane + 32 * i;
        if (idx < PPSQ) cnt += (p[idx] != 0.0f);
    }
#pragma unroll
    for (int off = 16; off; off >>= 1)
        cnt += __shfl_xor_sync(0xffffffffu, cnt, off);

    if (lane == 0)
        g_invnz[warp_global] = 1.0f / ((float)cnt + 1e-5f);
}

// ---------------------------------------------------------------------------
// Kernel 2: fused GEMM (128 x 128 x 128 tile) + attention epilogue.
//   Grid: NVOX/128 = 1458 CTAs, 256 threads each.
//   Each CTA: all 128 out-channels x 128 consecutive voxels.
//   Thread (tx, ty) in 16x16: 8 oc x 8 voxels micro-tile,
//     oc = ty + 16*i,  v = v0 + tx + 16*j   (coalesced epilogue loads/stores)
// ---------------------------------------------------------------------------
__global__ __launch_bounds__(256) void fused_kernel(
    const float* __restrict__ x,
    const float* __restrict__ att,
    const float* __restrict__ W,
    const float* __restrict__ b,
    float* __restrict__ out)
{
    extern __shared__ float smem[];
    float* sW = smem;                 // sW[k][oc], row stride 129 (transposed W)
    float* sX = smem + 128 * 129;     // sX[k][v],  row stride 129

    const int tid = threadIdx.x;
    const int tx = tid & 15;
    const int ty = tid >> 4;
    const int v0 = blockIdx.x * 128;

    // accumulators, init with bias
    float acc[8][8];
#pragma unroll
    for (int i = 0; i < 8; i++) {
        float bb = b[ty + 16 * i];
#pragma unroll
        for (int j = 0; j < 8; j++) acc[i][j] = bb;
    }

    // load W transposed: sW[k*129 + oc] = W[oc*128 + k]
    for (int i = tid; i < 128 * 128; i += 256) {
        int oc = i >> 7;
        int k  = i & 127;
        sW[k * 129 + oc] = W[i];
    }
    // load X tile: sX[k*129 + v] = x[k*NVOX + v0 + v]
    {
        const float* xt = x + (size_t)v0;
        for (int i = tid; i < 128 * 128; i += 256) {
            int k = i >> 7;
            int v = i & 127;
            sX[k * 129 + v] = xt[(size_t)k * NVOX + v];
        }
    }
    __syncthreads();

    // main GEMM loop over k
#pragma unroll 4
    for (int k = 0; k < 128; k++) {
        float a[8], bx[8];
        const float* wk = sW + k * 129;
        const float* xk = sX + k * 129;
#pragma unroll
        for (int i = 0; i < 8; i++) a[i] = wk[ty + 16 * i];
#pragma unroll
        for (int j = 0; j < 8; j++) bx[j] = xk[tx + 16 * j];
#pragma unroll
        for (int i = 0; i < 8; i++)
#pragma unroll
            for (int j = 0; j < 8; j++)
                acc[i][j] = fmaf(a[i], bx[j], acc[i][j]);
    }

    // fused epilogue: out = leaky( y * (y + att/nz + 1) )
#pragma unroll
    for (int j = 0; j < 8; j++) {
        int v  = v0 + tx + 16 * j;
        int d  = v / HWDIM;
        int hw = v - d * HWDIM;
        int id = d / PATCH,  pd = d  - id * PATCH;
        int iw = hw / PATCH, pw = hw - iw * PATCH;
        int l  = id * NW + iw;
        int pp = pd * PATCH + pw;
        size_t attoff = (size_t)l * PPSQ + pp;
#pragma unroll
        for (int i = 0; i < 8; i++) {
            int oc = ty + 16 * i;
            float y = acc[i][j];
            float a = att[(size_t)oc * (LPATCH * PPSQ) + attoff]
                      * g_invnz[oc * LPATCH + l];
            float o = y * (y + a + 1.0f);
            out[(size_t)oc * NVOX + v] = (o >= 0.0f) ? o : 0.2f * o;
        }
    }
}

// ---------------------------------------------------------------------------
// kernel_launch
//   d_in[0] = x           (23887872 f32)
//   d_in[1] = attentions  (23887872 f32)
//   d_in[2] = W           (16384 f32)
//   d_in[3] = b           (128 f32)
// ---------------------------------------------------------------------------
extern "C" void kernel_launch(void* const* d_in, const int* in_sizes, int n_in,
                              void* d_out, int out_size)
{
    (void)in_sizes; (void)n_in; (void)out_size;
    const float* x   = (const float*)d_in[0];
    const float* att = (const float*)d_in[1];
    const float* W   = (const float*)d_in[2];
    const float* b   = (const float*)d_in[3];
    float* out = (float*)d_out;

    // pass 1: inverse nonzero counts (294912 warps, 8 per CTA)
    nz_kernel<<<(COUT * LPATCH) / 8, 256>>>(att);

    // pass 2: fused GEMM + epilogue
    cudaFuncSetAttribute(fused_kernel,
                         cudaFuncAttributeMaxDynamicSharedMemorySize,
                         SMEM_BYTES);
    fused_kernel<<<NVOX / 128, 256, SMEM_BYTES>>>(x, att, W, b, out);
}

// round 2
// speedup vs baseline: 2.3386x; 2.3386x over previous
#include <cuda_runtime.h>
#include <cstdint>

// ---------------------------------------------------------------------------
//   x:   [1, 128, 36, 72, 72]  fp32   (Cin=128, NVOX=186624)
//   att: [1, 128, 2304, 81]    fp32
//   W:   [128, 128] fp32, b: [128] fp32
//   y   = W @ x + b
//   out = leaky_0.2( y * (y + att[c,l,pp]/nz[c,l] + 1) )
// ---------------------------------------------------------------------------

#define CIN    128
#define COUT   128
#define DDIM   36
#define HWDIM  5184
#define NVOX   (DDIM * HWDIM)     // 186624
#define PATCH  9
#define PPSQ   81
#define NW     (HWDIM / PATCH)    // 576
#define LPATCH 2304

#define TILE_V 256
#define THREADS 512
#define SMEM_BYTES ((128 * 128 + 128 * TILE_V) * 4)   // 64KB + 128KB = 192KB

__device__ float g_invnz[COUT * LPATCH];   // 1/(nnz + 1e-5)
__device__ float g_Wt[CIN * COUT];         // W transposed: [k][oc]

// ---------------------------------------------------------------------------
// packed fp32x2 helpers (Blackwell FFMA2 — 2x FFMA throughput, rt_SMSP = 2)
// ---------------------------------------------------------------------------
__device__ __forceinline__ unsigned long long ffma2(unsigned long long a,
                                                    unsigned long long b,
                                                    unsigned long long c)
{
    unsigned long long d;
    asm("fma.rn.f32x2 %0, %1, %2, %3;" : "=l"(d) : "l"(a), "l"(b), "l"(c));
    return d;
}
__device__ __forceinline__ unsigned long long dup2(float f)
{
    unsigned long long d;
    asm("mov.b64 %0, {%1, %1};" : "=l"(d) : "f"(f));
    return d;
}
__device__ __forceinline__ float2 unpack2(unsigned long long v)
{
    float2 r;
    asm("mov.b64 {%0, %1}, %2;" : "=f"(r.x), "=f"(r.y) : "l"(v));
    return r;
}

// ---------------------------------------------------------------------------
// Kernel 1: inverse nonzero counts (one warp per (c,l) row of 81)
//           + transpose W into g_Wt (first 64 blocks)
// ---------------------------------------------------------------------------
__global__ __launch_bounds__(256) void nz_kernel(const float* __restrict__ att,
                                                 const float* __restrict__ W)
{
    if (blockIdx.x < 64) {
        int idx = blockIdx.x * 256 + threadIdx.x;   // 0..16383
        int oc = idx >> 7, k = idx & 127;
        g_Wt[k * 128 + oc] = W[idx];
    }

    int warp_global = (blockIdx.x * blockDim.x + threadIdx.x) >> 5;
    int lane = threadIdx.x & 31;
    if (warp_global >= COUT * LPATCH) return;

    const float* p = att + (size_t)warp_global * PPSQ;
    int cnt = 0;
#pragma unroll
    for (int i = 0; i < 3; i++) {
        int idx = lane + 32 * i;
        if (idx < PPSQ) cnt += (p[idx] != 0.0f);
    }
#pragma unroll
    for (int off = 16; off; off >>= 1)
        cnt += __shfl_xor_sync(0xffffffffu, cnt, off);

    if (lane == 0)
        g_invnz[warp_global] = 1.0f / ((float)cnt + 1e-5f);
}

// ---------------------------------------------------------------------------
// Kernel 2: fused GEMM (128 oc x 256 vox per CTA) + epilogue, FFMA2 inner loop
//   512 threads: warp = one oc-group (ocb = wid*8), lanes cover 256 vox as
//   two float4 chunks (lane*4, lane*4+128). Per-thread micro-tile 8x8.
// ---------------------------------------------------------------------------
__global__ __launch_bounds__(THREADS, 1) void fused_kernel(
    const float* __restrict__ x,
    const float* __restrict__ att,
    const float* __restrict__ b,
    float* __restrict__ out)
{
    extern __shared__ float smem[];
    float* sW = smem;                  // [k][oc], 128x128, no pad
    float* sX = smem + 128 * 128;      // [k][v],  128x256, no pad

    const int tid  = threadIdx.x;
    const int lane = tid & 31;
    const int wid  = tid >> 5;         // 0..15
    const int ocb  = wid * 8;
    const int v0   = blockIdx.x * TILE_V;

    // --- load W (already transposed in gmem) : coalesced float4 copy ---
    {
        const float4* Wv = (const float4*)g_Wt;
        float4* sWv = (float4*)sW;
#pragma unroll
        for (int i = 0; i < 8; i++)                 // 4096 float4
            sWv[tid + THREADS * i] = Wv[tid + THREADS * i];
    }
    // --- load X tile: sX[k*256 + v] = x[k*NVOX + v0 + v], float4 ---
    {
        float4* sXv = (float4*)sX;
#pragma unroll
        for (int i = 0; i < 16; i++) {              // 8192 float4
            int t  = tid + THREADS * i;
            int k  = t >> 6;
            int v4 = t & 63;
            sXv[t] = *(const float4*)(x + (size_t)k * NVOX + v0 + v4 * 4);
        }
    }

    // --- accumulators (f32x2 pairs), init with bias ---
    unsigned long long acc[8][4];
#pragma unroll
    for (int i = 0; i < 8; i++) {
        unsigned long long bd = dup2(b[ocb + i]);
#pragma unroll
        for (int q = 0; q < 4; q++) acc[i][q] = bd;
    }

    __syncthreads();

    // --- main GEMM loop over k (FFMA2: 32 packed FMAs per k per thread) ---
#pragma unroll 2
    for (int k = 0; k < 128; k++) {
        const float* wk = sW + k * 128 + ocb;
        unsigned long long ad[8];
#pragma unroll
        for (int i = 0; i < 8; i++) ad[i] = dup2(wk[i]);   // broadcast LDS

        const ulonglong2* xk =
            (const ulonglong2*)(sX + k * TILE_V + lane * 4);
        ulonglong2 b0 = xk[0];      // vox lane*4 + {0,1},{2,3}
        ulonglong2 b1 = xk[32];     // vox lane*4 + 128 + {0,1},{2,3}
        unsigned long long bb[4] = { b0.x, b0.y, b1.x, b1.y };

#pragma unroll
        for (int i = 0; i < 8; i++)
#pragma unroll
            for (int q = 0; q < 4; q++)
                acc[i][q] = ffma2(ad[i], bb[q], acc[i][q]);
    }

    // --- epilogue: out = leaky( y * (y + att/nz + 1) ) ---
    const int vbase = v0 + lane * 4;
    int l_[8], po_[8];
#pragma unroll
    for (int m = 0; m < 2; m++)
#pragma unroll
        for (int j = 0; j < 4; j++) {
            int v  = vbase + 128 * m + j;
            int d  = v / HWDIM;
            int hw = v - d * HWDIM;
            int id = d / PATCH,  pd = d  - id * PATCH;
            int iw = hw / PATCH, pw = hw - iw * PATCH;
            l_[m * 4 + j]  = id * NW + iw;
            po_[m * 4 + j] = pd * PATCH + pw;
        }

#pragma unroll
    for (int i = 0; i < 8; i++) {
        int oc = ocb + i;
        const float* attp = att + (size_t)oc * (LPATCH * PPSQ);
        const float* inz  = g_invnz + oc * LPATCH;

        float r[8];
#pragma unroll
        for (int q = 0; q < 4; q++) {
            float2 t = unpack2(acc[i][q]);
            int s = (q >> 1) * 4 + (q & 1) * 2;
            {
                float a = attp[(size_t)l_[s] * PPSQ + po_[s]] * inz[l_[s]];
                float o = t.x * (t.x + a + 1.0f);
                r[s] = (o >= 0.0f) ? o : 0.2f * o;
            }
            {
                float a = attp[(size_t)l_[s + 1] * PPSQ + po_[s + 1]] * inz[l_[s + 1]];
                float o = t.y * (t.y + a + 1.0f);
                r[s + 1] = (o >= 0.0f) ? o : 0.2f * o;
            }
        }
        // two coalesced float4 stores per oc
        *(float4*)(out + (size_t)oc * NVOX + vbase) =
            make_float4(r[0], r[1], r[2], r[3]);
        *(float4*)(out + (size_t)oc * NVOX + vbase + 128) =
            make_float4(r[4], r[5], r[6], r[7]);
    }
}

// ---------------------------------------------------------------------------
extern "C" void kernel_launch(void* const* d_in, const int* in_sizes, int n_in,
                              void* d_out, int out_size)
{
    (void)in_sizes; (void)n_in; (void)out_size;
    const float* x   = (const float*)d_in[0];
    const float* att = (const float*)d_in[1];
    const float* W   = (const float*)d_in[2];
    const float* b   = (const float*)d_in[3];
    float* out = (float*)d_out;

    nz_kernel<<<(COUT * LPATCH) / 8, 256>>>(att, W);

    cudaFuncSetAttribute(fused_kernel,
                         cudaFuncAttributeMaxDynamicSharedMemorySize,
                         SMEM_BYTES);
    fused_kernel<<<NVOX / TILE_V, THREADS, SMEM_BYTES>>>(x, att, b, out);
}

// round 4
// speedup vs baseline: 2.5262x; 1.0802x over previous
#include <cuda_runtime.h>
#include <cuda_bf16.h>
#include <cstdint>

// ---------------------------------------------------------------------------
//   y   = W @ x + b   (oc=128, cin=128, vox=186624)
//   out = leaky_0.2( y * (y + att[c,l,pp]/nz[c,l] + 1) )
// GEMM on mma.sync m16n8k16 (bf16, HMMA) via 3-way split:
//   W*x ~= Wh*xh + Wh*xl + Wl*xh   (fp32 accumulate)
// (tcgen05 unavailable: harness builds for plain sm_103, no 'a' features)
// ---------------------------------------------------------------------------

#define CIN    128
#define COUT   128
#define HWDIM  5184
#define NVOX   186624
#define PATCH  9
#define PPSQ   81
#define NW     576
#define LPATCH 2304

#define TILE_V  256
#define THREADS 512

// dynamic smem layout (bytes): xh[256][128]bf16, xl same, Wh[128][128]bf16, Wl
#define SM_XH 0
#define SM_XL 65536
#define SM_W  131072
#define SMEM_TOTAL 196608

__device__ float g_invnz[COUT * LPATCH];                // 1/(nnz + 1e-5)
__device__ __align__(16) unsigned short g_Wsw[32768];   // [Wh 16K][Wl 16K], swizzled

// ---------------------------------------------------------------------------
// helpers
// ---------------------------------------------------------------------------
__device__ __forceinline__ uint32_t smem_u32(const void* p) {
    uint32_t a;
    asm("{ .reg .u64 t; cvta.to.shared.u64 t, %1; cvt.u32.u64 %0, t; }"
        : "=r"(a) : "l"(p));
    return a;
}
// pack two fp32 -> bf16x2 (lo in low half = lower k index)
__device__ __forceinline__ uint32_t pack_bf16x2(float lo, float hi) {
    uint32_t r;
    asm("cvt.rn.bf16x2.f32 %0, %1, %2;" : "=r"(r) : "f"(hi), "f"(lo));
    return r;
}
__device__ __forceinline__ void sts64(uint32_t addr, uint32_t a, uint32_t b) {
    asm volatile("st.shared.v2.u32 [%0], {%1, %2};"
                 :: "r"(addr), "r"(a), "r"(b) : "memory");
}
__device__ __forceinline__ void ldsm_x4(uint32_t addr, uint32_t* r) {
    asm volatile("ldmatrix.sync.aligned.m8n8.x4.shared.b16 {%0,%1,%2,%3}, [%4];"
                 : "=r"(r[0]), "=r"(r[1]), "=r"(r[2]), "=r"(r[3]) : "r"(addr));
}
__device__ __forceinline__ void mma16816(float* d, const uint32_t* a,
                                         uint32_t b0, uint32_t b1) {
    asm volatile(
        "mma.sync.aligned.m16n8k16.row.col.f32.bf16.bf16.f32 "
        "{%0,%1,%2,%3}, {%4,%5,%6,%7}, {%8,%9}, {%0,%1,%2,%3};"
        : "+f"(d[0]), "+f"(d[1]), "+f"(d[2]), "+f"(d[3])
        : "r"(a[0]), "r"(a[1]), "r"(a[2]), "r"(a[3]), "r"(b0), "r"(b1));
}
// swizzled byte offset within a [row][k] bf16 tile, 256B rows, 16B-chunk xor
__device__ __forceinline__ uint32_t swz(int row, uint32_t kbyte) {
    return (uint32_t)row * 256u + (kbyte ^ (uint32_t)((row & 7) << 4));
}

// ---------------------------------------------------------------------------
// Prep kernel: W bf16 hi/lo split (swizzled) + inverse nonzero counts.
// nz: one warp per (c,l) row of 81 (verified R2 logic).
// ---------------------------------------------------------------------------
__global__ __launch_bounds__(256) void prep_kernel(const float* __restrict__ att,
                                                   const float* __restrict__ W)
{
    const int tid = threadIdx.x;
    const int blk = blockIdx.x;

    if (blk < 64) {   // W split, 64*256 = 16384 elements
        int idx = blk * 256 + tid;
        int oc = idx >> 7, k = idx & 127;
        float w = W[idx];
        __nv_bfloat16 h = __float2bfloat16(w);
        float hf = __bfloat162float(h);
        __nv_bfloat16 l = __float2bfloat16(w - hf);
        uint32_t off = swz(oc, (uint32_t)(k * 2)) >> 1;
        g_Wsw[off]         = *(unsigned short*)&h;
        g_Wsw[off + 16384] = *(unsigned short*)&l;
    }

    int warp_global = (blk * 256 + tid) >> 5;
    int lane = tid & 31;
    if (warp_global >= COUT * LPATCH) return;

    const float* p = att + (size_t)warp_global * PPSQ;
    int cnt = 0;
#pragma unroll
    for (int i = 0; i < 3; i++) {
        int idx = lane + 32 * i;
        if (idx < PPSQ) cnt += (p[idx] != 0.0f);
    }
#pragma unroll
    for (int off = 16; off; off >>= 1)
        cnt += __shfl_xor_sync(0xffffffffu, cnt, off);

    if (lane == 0)
        g_invnz[warp_global] = 1.0f / ((float)cnt + 1e-5f);
}

// ---------------------------------------------------------------------------
// Fused kernel: 128 oc x 256 vox per CTA.
//   16 warps: ocb = (wid&3)*32, vh = (wid>>2)*64. Warp tile 32oc x 64vox.
// ---------------------------------------------------------------------------
__global__ __launch_bounds__(THREADS, 1)
void fused_kernel(const float* __restrict__ x,
                  const float* __restrict__ att,
                  const float* __restrict__ b,
                  float* __restrict__ out)
{
    extern __shared__ __align__(16) char smem[];
    const uint32_t sbase = smem_u32(smem);
    const int tid  = threadIdx.x;
    const int lane = tid & 31;
    const int wid  = tid >> 5;
    const int v0   = blockIdx.x * TILE_V;

    // --- copy pre-swizzled W hi/lo (64KB) to smem ---
    {
        const float4* Wv = (const float4*)g_Wsw;
        float4* sWv = (float4*)(smem + SM_W);
#pragma unroll
        for (int i = 0; i < 8; i++)
            sWv[tid + THREADS * i] = Wv[tid + THREADS * i];
    }

    // --- load x tile (fp32, coalesced) -> bf16 hi/lo -> swizzled smem ---
    {
        const int vt = tid & 255;
        const float* xp = x + (size_t)v0 + vt;
        const uint32_t rowbase = (uint32_t)vt * 256u;
        const uint32_t swm = (uint32_t)((vt & 7) << 4);
#pragma unroll 4
        for (int it = 0; it < 16; it++) {
            int k0 = (tid >> 8) * 4 + it * 8;
            float f0 = xp[(size_t)(k0 + 0) * NVOX];
            float f1 = xp[(size_t)(k0 + 1) * NVOX];
            float f2 = xp[(size_t)(k0 + 2) * NVOX];
            float f3 = xp[(size_t)(k0 + 3) * NVOX];
            uint32_t h01 = pack_bf16x2(f0, f1);
            uint32_t h23 = pack_bf16x2(f2, f3);
            float h0 = __uint_as_float(h01 << 16);
            float h1 = __uint_as_float(h01 & 0xffff0000u);
            float h2 = __uint_as_float(h23 << 16);
            float h3 = __uint_as_float(h23 & 0xffff0000u);
            uint32_t l01 = pack_bf16x2(f0 - h0, f1 - h1);
            uint32_t l23 = pack_bf16x2(f2 - h2, f3 - h3);
            uint32_t off = rowbase + (((uint32_t)(k0 * 2)) ^ swm);
            sts64(sbase + SM_XH + off, h01, h23);
            sts64(sbase + SM_XL + off, l01, l23);
        }
    }
    __syncthreads();

    // --- accumulators, init with bias ---
    const int ocb = (wid & 3) * 32;
    const int vh  = (wid >> 2) * 64;
    const int ocl = ocb + (lane >> 2);       // lane/4 : 0..7

    float acc[2][8][4];
#pragma unroll
    for (int t = 0; t < 2; t++) {
        float b0 = __ldg(b + ocl + 16 * t);
        float b1 = __ldg(b + ocl + 16 * t + 8);
#pragma unroll
        for (int nb = 0; nb < 8; nb++) {
            acc[t][nb][0] = b0; acc[t][nb][1] = b0;
            acc[t][nb][2] = b1; acc[t][nb][3] = b1;
        }
    }

    // --- ldmatrix lane addressing ---
    // A (x4): lanes0-7 rows m0-7@k0 | 8-15 m8-15@k0 | 16-23 m0-7@k0+8 | 24-31 m8-15@k0+8
    const int aRow = ocb + (lane & 15);
    const uint32_t aSw = (uint32_t)((aRow & 7) << 4);   // same for row+16
    const uint32_t aK  = (uint32_t)((lane >> 4) * 16);
    const uint32_t aB  = sbase + SM_W + (uint32_t)aRow * 256u;
    // B (x4): lanes0-7 n0-7@k0 | 8-15 n0-7@k0+8 | 16-23 n8-15@k0 | 24-31 n8-15@k0+8
    const int bRow = (lane & 7) + ((lane >> 4) & 1) * 8;
    const uint32_t bSw = (uint32_t)((bRow & 7) << 4);
    const uint32_t bK  = (uint32_t)(((lane >> 3) & 1) * 16);
    uint32_t bB[4];
#pragma unroll
    for (int nbp = 0; nbp < 4; nbp++)
        bB[nbp] = sbase + (uint32_t)(vh + nbp * 16 + bRow) * 256u;

    // --- main GEMM: 8 k-steps of k16 ---
#pragma unroll
    for (int ks = 0; ks < 8; ks++) {
        const uint32_t kbA = ((uint32_t)(ks * 32) + aK) ^ aSw;
        uint32_t a0h[4], a1h[4], a0l[4], a1l[4];
        ldsm_x4(aB + kbA,                 a0h);
        ldsm_x4(aB + 4096 + kbA,          a1h);
        ldsm_x4(aB + 32768 + kbA,         a0l);
        ldsm_x4(aB + 32768 + 4096 + kbA,  a1l);

        const uint32_t kbB = ((uint32_t)(ks * 32) + bK) ^ bSw;
#pragma unroll
        for (int nbp = 0; nbp < 4; nbp++) {
            uint32_t bh[4], bl[4];
            ldsm_x4(bB[nbp] + SM_XH + kbB, bh);
            ldsm_x4(bB[nbp] + SM_XL + kbB, bl);
            // n-block 2*nbp  (regs 0,1)
            mma16816(acc[0][2 * nbp],     a0h, bh[0], bh[1]);
            mma16816(acc[1][2 * nbp],     a1h, bh[0], bh[1]);
            mma16816(acc[0][2 * nbp],     a0h, bl[0], bl[1]);
            mma16816(acc[1][2 * nbp],     a1h, bl[0], bl[1]);
            mma16816(acc[0][2 * nbp],     a0l, bh[0], bh[1]);
            mma16816(acc[1][2 * nbp],     a1l, bh[0], bh[1]);
            // n-block 2*nbp+1 (regs 2,3)
            mma16816(acc[0][2 * nbp + 1], a0h, bh[2], bh[3]);
            mma16816(acc[1][2 * nbp + 1], a1h, bh[2], bh[3]);
            mma16816(acc[0][2 * nbp + 1], a0h, bl[2], bl[3]);
            mma16816(acc[1][2 * nbp + 1], a1h, bl[2], bl[3]);
            mma16816(acc[0][2 * nbp + 1], a0l, bh[2], bh[3]);
            mma16816(acc[1][2 * nbp + 1], a1l, bh[2], bh[3]);
        }
    }

    // --- epilogue, direct from C fragments (pairs = 2 consecutive voxels) ---
    const int voxbase = v0 + vh + 2 * (lane & 3);
#pragma unroll
    for (int t = 0; t < 2; t++) {
        const int oc0 = ocl + 16 * t;
        const int oc1 = oc0 + 8;
        const float* att0 = att + (size_t)oc0 * (LPATCH * PPSQ);
        const float* att1 = att + (size_t)oc1 * (LPATCH * PPSQ);
        const float* inz0 = g_invnz + oc0 * LPATCH;
        const float* inz1 = g_invnz + oc1 * LPATCH;
        float* o0 = out + (size_t)oc0 * NVOX;
        float* o1 = out + (size_t)oc1 * NVOX;
#pragma unroll
        for (int nb = 0; nb < 8; nb++) {
            const int v = voxbase + nb * 8;          // even; v,v+1 same d-plane
            int d  = v / HWDIM;
            int hw = v - d * HWDIM;
            int id = d / PATCH,  pd = d  - id * PATCH;
            int iw = hw / PATCH, pw = hw - iw * PATCH;
            int l0 = id * NW + iw, p0 = pd * PATCH + pw;
            int l1, p1;
            if (pw == PATCH - 1) { l1 = l0 + 1; p1 = pd * PATCH; }
            else                 { l1 = l0;     p1 = p0 + 1; }

            float a00 = att0[(size_t)l0 * PPSQ + p0] * inz0[l0];
            float a01 = att0[(size_t)l1 * PPSQ + p1] * inz0[l1];
            float a10 = att1[(size_t)l0 * PPSQ + p0] * inz1[l0];
            float a11 = att1[(size_t)l1 * PPSQ + p1] * inz1[l1];

            float y;
            float2 r;
            y = acc[t][nb][0]; r.x = y * (y + a00 + 1.0f);
            r.x = (r.x >= 0.0f) ? r.x : 0.2f * r.x;
            y = acc[t][nb][1]; r.y = y * (y + a01 + 1.0f);
            r.y = (r.y >= 0.0f) ? r.y : 0.2f * r.y;
            *(float2*)(o0 + v) = r;

            y = acc[t][nb][2]; r.x = y * (y + a10 + 1.0f);
            r.x = (r.x >= 0.0f) ? r.x : 0.2f * r.x;
            y = acc[t][nb][3]; r.y = y * (y + a11 + 1.0f);
            r.y = (r.y >= 0.0f) ? r.y : 0.2f * r.y;
            *(float2*)(o1 + v) = r;
        }
    }
}

// ---------------------------------------------------------------------------
extern "C" void kernel_launch(void* const* d_in, const int* in_sizes, int n_in,
                              void* d_out, int out_size)
{
    (void)in_sizes; (void)n_in; (void)out_size;
    const float* x   = (const float*)d_in[0];
    const float* att = (const float*)d_in[1];
    const float* W   = (const float*)d_in[2];
    const float* b   = (const float*)d_in[3];
    float* out = (float*)d_out;

    // 36864 CTAs x 8 warps = 294912 (c,l) rows; first 64 CTAs also split W
    prep_kernel<<<(COUT * LPATCH) / 8, 256>>>(att, W);

    cudaFuncSetAttribute(fused_kernel,
                         cudaFuncAttributeMaxDynamicSharedMemorySize,
                         SMEM_TOTAL);
    fused_kernel<<<NVOX / TILE_V, THREADS, SMEM_TOTAL>>>(x, att, b, out);
}